// round 1
// baseline (speedup 1.0000x reference)
#include <cuda_runtime.h>
#include <math.h>

#define Bc   4
#define C    48
#define C3   144
#define HH   256
#define WW   256
#define NPIX 65536   // HH*WW

// ---- scratch (device globals: no allocation allowed) ----
__device__ float g_qkv[(size_t)Bc * C3 * NPIX];   // after 1x1 conv (151 MB)
__device__ float g_dw [(size_t)Bc * C3 * NPIX];   // after depthwise (151 MB)
// per batch: gram[48*48] | qss[48] | kss[48]  => 2400 floats
__device__ float g_small[Bc * (C * C + 2 * C)];
__device__ float g_M[Bc * C * C];                 // (proj @ attn) per batch

// ============================================================
// K1: qkv 1x1 conv: out[b,oc,p] = sum_ic W[oc,ic] * x[b,ic,p]
// 256 threads, 2 pixels/thread (512 px per block); x in registers, W in smem.
// ============================================================
__global__ __launch_bounds__(256) void k_qkv(const float* __restrict__ x,
                                             const float* __restrict__ w) {
    __shared__ float Ws[C3 * C];  // 6912 floats = 27.6 KB
    const int tid = threadIdx.x;
    for (int i = tid; i < C3 * C; i += 256) Ws[i] = w[i];
    __syncthreads();

    const int blocksPerBatch = NPIX / 512;
    const int b = blockIdx.x / blocksPerBatch;
    const int pbase = (blockIdx.x % blocksPerBatch) * 512 + tid * 2;

    const float* xb = x + (size_t)b * C * NPIX + pbase;
    float xv0[C], xv1[C];
#pragma unroll
    for (int ic = 0; ic < C; ic++) {
        float2 v = *(const float2*)(xb + (size_t)ic * NPIX);
        xv0[ic] = v.x; xv1[ic] = v.y;
    }

    float* ob = g_qkv + (size_t)b * C3 * NPIX + pbase;
    for (int oc = 0; oc < C3; oc++) {
        float a0 = 0.f, a1 = 0.f;
        const float4* wp = (const float4*)(Ws + oc * C);
#pragma unroll
        for (int i4 = 0; i4 < C / 4; i4++) {
            float4 wv = wp[i4];
            a0 += wv.x * xv0[i4 * 4 + 0]; a1 += wv.x * xv1[i4 * 4 + 0];
            a0 += wv.y * xv0[i4 * 4 + 1]; a1 += wv.y * xv1[i4 * 4 + 1];
            a0 += wv.z * xv0[i4 * 4 + 2]; a1 += wv.z * xv1[i4 * 4 + 2];
            a0 += wv.w * xv0[i4 * 4 + 3]; a1 += wv.w * xv1[i4 * 4 + 3];
        }
        float2 o; o.x = a0; o.y = a1;
        *(float2*)(ob + (size_t)oc * NPIX) = o;
    }
}

// ============================================================
// K2: depthwise 3x3, zero pad 1. One block = one (b,ch,4-row tile).
// 256 threads = one per column; 6 input rows staged in smem.
// ============================================================
__global__ __launch_bounds__(256) void k_dw(const float* __restrict__ w) {
    const int ytile = blockIdx.x & 63;             // 64 tiles of 4 rows
    const int ch    = (blockIdx.x >> 6) % C3;
    const int b     = blockIdx.x / (64 * C3);
    const int tid   = threadIdx.x;

    const float* in  = g_qkv + ((size_t)b * C3 + ch) * NPIX;
    float*       out = g_dw  + ((size_t)b * C3 + ch) * NPIX;

    __shared__ float rows[6][WW];
    const int y0 = ytile * 4;
#pragma unroll
    for (int r = 0; r < 6; r++) {
        int y = y0 - 1 + r;
        rows[r][tid] = (y >= 0 && y < HH) ? in[y * WW + tid] : 0.f;
    }
    __syncthreads();

    const float w00 = w[ch*9+0], w01 = w[ch*9+1], w02 = w[ch*9+2];
    const float w10 = w[ch*9+3], w11 = w[ch*9+4], w12 = w[ch*9+5];
    const float w20 = w[ch*9+6], w21 = w[ch*9+7], w22 = w[ch*9+8];

    const int xq = tid;
    const float lm = (xq > 0) ? 1.f : 0.f;
    const float rm = (xq < WW - 1) ? 1.f : 0.f;
    const int xl = max(xq - 1, 0), xr = min(xq + 1, WW - 1);

#pragma unroll
    for (int r = 0; r < 4; r++) {
        float acc =
            w00 * rows[r    ][xl] * lm + w01 * rows[r    ][xq] + w02 * rows[r    ][xr] * rm +
            w10 * rows[r + 1][xl] * lm + w11 * rows[r + 1][xq] + w12 * rows[r + 1][xr] * rm +
            w20 * rows[r + 2][xl] * lm + w21 * rows[r + 2][xq] + w22 * rows[r + 2][xr] * rm;
        out[(y0 + r) * WW + xq] = acc;
    }
}

// ============================================================
// K3: Gram G = Q K^T  (48x48) + squared norms, per batch.
// 16x16 thread tile, each thread a 3x3 output block; padded smem (pitch 65)
// keeps column reads conflict-free. Atomic reduce into g_small.
// ============================================================
#define TS    64
#define CHUNK 1024
__global__ __launch_bounds__(256) void k_gram() {
    const int chunks = NPIX / CHUNK;  // 64
    const int b     = blockIdx.x / chunks;
    const int cbase = (blockIdx.x % chunks) * CHUNK;

    __shared__ float Qs[C][TS + 1], Ks[C][TS + 1];
    const int tid = threadIdx.x;
    const int c0 = (tid >> 4) * 3;   // 0..45
    const int d0 = (tid & 15) * 3;   // 0..45

    const float* Q = g_dw + (size_t)b * C3 * NPIX;                       // ch 0..47
    const float* K = g_dw + (size_t)b * C3 * NPIX + (size_t)C * NPIX;    // ch 48..95

    float acc[3][3] = {};
    float sq = 0.f;

    for (int sub = 0; sub < CHUNK / TS; sub++) {
        const int tb = cbase + sub * TS;
        for (int i = tid; i < C * TS; i += 256) {
            int cc = i / TS, t = i % TS;
            Qs[cc][t] = Q[(size_t)cc * NPIX + tb + t];
            Ks[cc][t] = K[(size_t)cc * NPIX + tb + t];
        }
        __syncthreads();
#pragma unroll 4
        for (int t = 0; t < TS; t++) {
            float q0 = Qs[c0][t], q1 = Qs[c0 + 1][t], q2 = Qs[c0 + 2][t];
            float k0 = Ks[d0][t], k1 = Ks[d0 + 1][t], k2 = Ks[d0 + 2][t];
            acc[0][0] += q0 * k0; acc[0][1] += q0 * k1; acc[0][2] += q0 * k2;
            acc[1][0] += q1 * k0; acc[1][1] += q1 * k1; acc[1][2] += q1 * k2;
            acc[2][0] += q2 * k0; acc[2][1] += q2 * k1; acc[2][2] += q2 * k2;
            if (tid < C)            { float v = Qs[tid][t];     sq += v * v; }
            else if (tid < 2 * C)   { float v = Ks[tid - C][t]; sq += v * v; }
        }
        __syncthreads();
    }

    float* gbase = g_small + b * (C * C + 2 * C);
#pragma unroll
    for (int i = 0; i < 3; i++)
#pragma unroll
        for (int j = 0; j < 3; j++)
            atomicAdd(&gbase[(c0 + i) * C + (d0 + j)], acc[i][j]);
    if (tid < 2 * C) atomicAdd(&gbase[C * C + tid], sq);  // qss then kss
}

// ============================================================
// K4: softmax(G/(qn*kn)*T) then M = proj @ attn. One block per batch.
// ============================================================
__global__ __launch_bounds__(256) void k_attn(const float* __restrict__ proj,
                                              const float* __restrict__ temp) {
    const int b = blockIdx.x;
    const int tid = threadIdx.x;
    __shared__ float attn[C][C];
    __shared__ float qn[C], kn[C];
    const float* gbase = g_small + b * (C * C + 2 * C);
    const float T = temp[0];

    if (tid < C)            qn[tid]     = fmaxf(sqrtf(gbase[C * C + tid]), 1e-12f);
    else if (tid < 2 * C)   kn[tid - C] = fmaxf(sqrtf(gbase[C * C + tid]), 1e-12f);
    __syncthreads();

    if (tid < C) {
        const int r = tid;
        float s[C];
        float mx = -1e30f;
        const float qinv = 1.f / qn[r];
#pragma unroll
        for (int d = 0; d < C; d++) {
            float v = gbase[r * C + d] * qinv / kn[d] * T;
            s[d] = v; mx = fmaxf(mx, v);
        }
        float sum = 0.f;
#pragma unroll
        for (int d = 0; d < C; d++) { s[d] = expf(s[d] - mx); sum += s[d]; }
        const float inv = 1.f / sum;
#pragma unroll
        for (int d = 0; d < C; d++) attn[r][d] = s[d] * inv;
    }
    __syncthreads();

    for (int i = tid; i < C * C; i += blockDim.x) {
        const int oc = i / C, d = i % C;
        float a = 0.f;
#pragma unroll
        for (int cc = 0; cc < C; cc++) a += proj[oc * C + cc] * attn[cc][d];
        g_M[b * C * C + i] = a;
    }
}

// ============================================================
// K5: out[b,oc,p] = sum_c M[b,oc,c] * V[b,c,p]   (writes d_out directly)
// ============================================================
__global__ __launch_bounds__(256) void k_out(float* __restrict__ out) {
    __shared__ float Ms[C * C];
    const int tid = threadIdx.x;
    const int blocksPerBatch = NPIX / 512;
    const int b = blockIdx.x / blocksPerBatch;
    const int pbase = (blockIdx.x % blocksPerBatch) * 512 + tid * 2;

    for (int i = tid; i < C * C; i += 256) Ms[i] = g_M[b * C * C + i];
    __syncthreads();

    const float* vb = g_dw + (size_t)b * C3 * NPIX + (size_t)(2 * C) * NPIX + pbase;
    float v0[C], v1[C];
#pragma unroll
    for (int cc = 0; cc < C; cc++) {
        float2 t = *(const float2*)(vb + (size_t)cc * NPIX);
        v0[cc] = t.x; v1[cc] = t.y;
    }

    float* ob = out + (size_t)b * C * NPIX + pbase;
    for (int oc = 0; oc < C; oc++) {
        float a0 = 0.f, a1 = 0.f;
        const float4* mp = (const float4*)(Ms + oc * C);
#pragma unroll
        for (int i4 = 0; i4 < C / 4; i4++) {
            float4 m = mp[i4];
            a0 += m.x * v0[i4 * 4 + 0]; a1 += m.x * v1[i4 * 4 + 0];
            a0 += m.y * v0[i4 * 4 + 1]; a1 += m.y * v1[i4 * 4 + 1];
            a0 += m.z * v0[i4 * 4 + 2]; a1 += m.z * v1[i4 * 4 + 2];
            a0 += m.w * v0[i4 * 4 + 3]; a1 += m.w * v1[i4 * 4 + 3];
        }
        float2 o; o.x = a0; o.y = a1;
        *(float2*)(ob + (size_t)oc * NPIX) = o;
    }
}

// ============================================================
extern "C" void kernel_launch(void* const* d_in, const int* in_sizes, int n_in,
                              void* d_out, int out_size) {
    const float* x      = (const float*)d_in[0];
    const float* qkv_w  = (const float*)d_in[1];
    const float* dw_w   = (const float*)d_in[2];
    const float* proj_w = (const float*)d_in[3];
    const float* temp   = (const float*)d_in[4];

    void* smallp = nullptr;
    cudaGetSymbolAddress(&smallp, g_small);
    cudaMemsetAsync(smallp, 0, sizeof(float) * Bc * (C * C + 2 * C));

    k_qkv <<<Bc * (NPIX / 512),   256>>>(x, qkv_w);
    k_dw  <<<Bc * C3 * (HH / 4),  256>>>(dw_w);
    k_gram<<<Bc * (NPIX / CHUNK), 256>>>();
    k_attn<<<Bc,                  256>>>(proj_w, temp);
    k_out <<<Bc * (NPIX / 512),   256>>>((float*)d_out);
}

// round 2
// speedup vs baseline: 1.1471x; 1.1471x over previous
#include <cuda_runtime.h>
#include <cuda_fp16.h>
#include <math.h>

#define Bc   4
#define C    48
#define C3   144
#define HH   256
#define WW   256
#define NPIX 65536   // HH*WW

// ---- scratch (device globals: no allocation allowed) ----
__device__ __half g_qkv[(size_t)Bc * C3 * NPIX];   // after 1x1 conv (75 MB)
__device__ __half g_dw [(size_t)Bc * C3 * NPIX];   // after depthwise (75 MB)
// per batch: gram[48*48] | qss[48] | kss[48]  => 2400 floats
__device__ float g_small[Bc * (C * C + 2 * C)];
__device__ float g_M[Bc * C * C];                  // (proj @ attn) per batch

// ============================================================
// K1: qkv 1x1 conv: out[b,oc,p] = sum_ic W[oc,ic] * x[b,ic,p]
// 256 threads, 2 pixels/thread; x in registers, W in smem. fp16 out.
// ============================================================
__global__ __launch_bounds__(256) void k_qkv(const float* __restrict__ x,
                                             const float* __restrict__ w) {
    __shared__ float Ws[C3 * C];  // 27.6 KB
    const int tid = threadIdx.x;
    for (int i = tid; i < C3 * C; i += 256) Ws[i] = w[i];
    __syncthreads();

    const int blocksPerBatch = NPIX / 512;
    const int b = blockIdx.x / blocksPerBatch;
    const int pbase = (blockIdx.x % blocksPerBatch) * 512 + tid * 2;

    const float* xb = x + (size_t)b * C * NPIX + pbase;
    float xv0[C], xv1[C];
#pragma unroll
    for (int ic = 0; ic < C; ic++) {
        float2 v = *(const float2*)(xb + (size_t)ic * NPIX);
        xv0[ic] = v.x; xv1[ic] = v.y;
    }

    __half* ob = g_qkv + (size_t)b * C3 * NPIX + pbase;
    for (int oc = 0; oc < C3; oc++) {
        float a0 = 0.f, a1 = 0.f;
        const float4* wp = (const float4*)(Ws + oc * C);
#pragma unroll
        for (int i4 = 0; i4 < C / 4; i4++) {
            float4 wv = wp[i4];
            a0 += wv.x * xv0[i4 * 4 + 0]; a1 += wv.x * xv1[i4 * 4 + 0];
            a0 += wv.y * xv0[i4 * 4 + 1]; a1 += wv.y * xv1[i4 * 4 + 1];
            a0 += wv.z * xv0[i4 * 4 + 2]; a1 += wv.z * xv1[i4 * 4 + 2];
            a0 += wv.w * xv0[i4 * 4 + 3]; a1 += wv.w * xv1[i4 * 4 + 3];
        }
        *(__half2*)(ob + (size_t)oc * NPIX) = __floats2half2_rn(a0, a1);
    }
}

// ============================================================
// K2: depthwise 3x3, zero pad 1. One block = one (b,ch,8-row tile).
// 256 threads = one per column; 10 input rows staged in smem (fp32).
// ============================================================
#define DWROWS 8
__global__ __launch_bounds__(256) void k_dw(const float* __restrict__ w) {
    const int tilesY = HH / DWROWS;                  // 32
    const int ytile = blockIdx.x & (tilesY - 1);
    const int ch    = (blockIdx.x / tilesY) % C3;
    const int b     = blockIdx.x / (tilesY * C3);
    const int tid   = threadIdx.x;

    const __half* in  = g_qkv + ((size_t)b * C3 + ch) * NPIX;
    __half*       out = g_dw  + ((size_t)b * C3 + ch) * NPIX;

    __shared__ float rows[DWROWS + 2][WW];
    const int y0 = ytile * DWROWS;
#pragma unroll
    for (int r = 0; r < DWROWS + 2; r++) {
        int y = y0 - 1 + r;
        rows[r][tid] = (y >= 0 && y < HH) ? __half2float(in[y * WW + tid]) : 0.f;
    }
    __syncthreads();

    const float w00 = w[ch*9+0], w01 = w[ch*9+1], w02 = w[ch*9+2];
    const float w10 = w[ch*9+3], w11 = w[ch*9+4], w12 = w[ch*9+5];
    const float w20 = w[ch*9+6], w21 = w[ch*9+7], w22 = w[ch*9+8];

    const int xq = tid;
    const float lm = (xq > 0) ? 1.f : 0.f;
    const float rm = (xq < WW - 1) ? 1.f : 0.f;
    const int xl = max(xq - 1, 0), xr = min(xq + 1, WW - 1);

#pragma unroll
    for (int r = 0; r < DWROWS; r++) {
        float acc =
            w00 * rows[r    ][xl] * lm + w01 * rows[r    ][xq] + w02 * rows[r    ][xr] * rm +
            w10 * rows[r + 1][xl] * lm + w11 * rows[r + 1][xq] + w12 * rows[r + 1][xr] * rm +
            w20 * rows[r + 2][xl] * lm + w21 * rows[r + 2][xq] + w22 * rows[r + 2][xr] * rm;
        out[(y0 + r) * WW + xq] = __float2half_rn(acc);
    }
}

// ============================================================
// K3: Gram G = Q K^T (48x48) + squared norms, per batch.
// 16x16 thread tile, 3x3 register block per thread; padded smem.
// ============================================================
#define TS    64
#define CHUNK 1024
__global__ __launch_bounds__(256) void k_gram() {
    const int chunks = NPIX / CHUNK;  // 64
    const int b     = blockIdx.x / chunks;
    const int cbase = (blockIdx.x % chunks) * CHUNK;

    __shared__ float Qs[C][TS + 1], Ks[C][TS + 1];
    const int tid = threadIdx.x;
    const int c0 = (tid >> 4) * 3;
    const int d0 = (tid & 15) * 3;

    const __half* Q = g_dw + (size_t)b * C3 * NPIX;
    const __half* K = g_dw + (size_t)b * C3 * NPIX + (size_t)C * NPIX;

    float acc[3][3] = {};
    float sq = 0.f;

    for (int sub = 0; sub < CHUNK / TS; sub++) {
        const int tb = cbase + sub * TS;
        // staged loads as half2
        for (int i = tid; i < C * (TS / 2); i += 256) {
            int cc = i / (TS / 2), t2 = i % (TS / 2);
            float2 qv = __half22float2(*(const __half2*)(Q + (size_t)cc * NPIX + tb + 2 * t2));
            float2 kv = __half22float2(*(const __half2*)(K + (size_t)cc * NPIX + tb + 2 * t2));
            Qs[cc][2 * t2] = qv.x; Qs[cc][2 * t2 + 1] = qv.y;
            Ks[cc][2 * t2] = kv.x; Ks[cc][2 * t2 + 1] = kv.y;
        }
        __syncthreads();
#pragma unroll 4
        for (int t = 0; t < TS; t++) {
            float q0 = Qs[c0][t], q1 = Qs[c0 + 1][t], q2 = Qs[c0 + 2][t];
            float k0 = Ks[d0][t], k1 = Ks[d0 + 1][t], k2 = Ks[d0 + 2][t];
            acc[0][0] += q0 * k0; acc[0][1] += q0 * k1; acc[0][2] += q0 * k2;
            acc[1][0] += q1 * k0; acc[1][1] += q1 * k1; acc[1][2] += q1 * k2;
            acc[2][0] += q2 * k0; acc[2][1] += q2 * k1; acc[2][2] += q2 * k2;
            if (tid < C)            { float v = Qs[tid][t];     sq += v * v; }
            else if (tid < 2 * C)   { float v = Ks[tid - C][t]; sq += v * v; }
        }
        __syncthreads();
    }

    float* gbase = g_small + b * (C * C + 2 * C);
#pragma unroll
    for (int i = 0; i < 3; i++)
#pragma unroll
        for (int j = 0; j < 3; j++)
            atomicAdd(&gbase[(c0 + i) * C + (d0 + j)], acc[i][j]);
    if (tid < 2 * C) atomicAdd(&gbase[C * C + tid], sq);
}

// ============================================================
// K4: softmax(G/(qn*kn)*T) then M = proj @ attn. One block per batch.
// Warp-per-row softmax: no register arrays, no spills.
// ============================================================
__global__ __launch_bounds__(256) void k_attn(const float* __restrict__ proj,
                                              const float* __restrict__ temp) {
    const int b = blockIdx.x;
    const int tid = threadIdx.x;
    const int warp = tid >> 5, lane = tid & 31;
    __shared__ float A[C][C + 1];
    __shared__ float qn[C], kn[C];
    const float* gbase = g_small + b * (C * C + 2 * C);
    const float T = temp[0];

    if (tid < C)          qn[tid]     = fmaxf(sqrtf(gbase[C * C + tid]), 1e-12f);
    else if (tid < 2 * C) kn[tid - C] = fmaxf(sqrtf(gbase[C * C + tid]), 1e-12f);
    __syncthreads();

    // scaled logits into smem
    for (int i = tid; i < C * C; i += 256) {
        int r = i / C, d = i % C;
        A[r][d] = gbase[i] * T / (qn[r] * kn[d]);
    }
    __syncthreads();

    // softmax: warp per row
    for (int r = warp; r < C; r += 8) {
        float v0 = A[r][lane];
        float v1 = (lane + 32 < C) ? A[r][lane + 32] : -1e30f;
        float mx = fmaxf(v0, v1);
#pragma unroll
        for (int o = 16; o > 0; o >>= 1) mx = fmaxf(mx, __shfl_xor_sync(~0u, mx, o));
        float e0 = expf(v0 - mx);
        float e1 = (lane + 32 < C) ? expf(v1 - mx) : 0.f;
        float s = e0 + e1;
#pragma unroll
        for (int o = 16; o > 0; o >>= 1) s += __shfl_xor_sync(~0u, s, o);
        float inv = 1.f / s;
        A[r][lane] = e0 * inv;
        if (lane + 32 < C) A[r][lane + 32] = e1 * inv;
    }
    __syncthreads();

    // M = proj @ attn
    for (int i = tid; i < C * C; i += 256) {
        const int oc = i / C, d = i % C;
        float a = 0.f;
#pragma unroll
        for (int cc = 0; cc < C; cc++) a += proj[oc * C + cc] * A[cc][d];
        g_M[b * C * C + i] = a;
    }
}

// ============================================================
// K5: out[b,oc,p] = sum_c M[b,oc,c] * V[b,c,p]   (writes d_out)
// ============================================================
__global__ __launch_bounds__(256) void k_out(float* __restrict__ out) {
    __shared__ float Ms[C * C];
    const int tid = threadIdx.x;
    const int blocksPerBatch = NPIX / 512;
    const int b = blockIdx.x / blocksPerBatch;
    const int pbase = (blockIdx.x % blocksPerBatch) * 512 + tid * 2;

    for (int i = tid; i < C * C; i += 256) Ms[i] = g_M[b * C * C + i];
    __syncthreads();

    const __half* vb = g_dw + (size_t)b * C3 * NPIX + (size_t)(2 * C) * NPIX + pbase;
    float v0[C], v1[C];
#pragma unroll
    for (int cc = 0; cc < C; cc++) {
        float2 t = __half22float2(*(const __half2*)(vb + (size_t)cc * NPIX));
        v0[cc] = t.x; v1[cc] = t.y;
    }

    float* ob = out + (size_t)b * C * NPIX + pbase;
    for (int oc = 0; oc < C; oc++) {
        float a0 = 0.f, a1 = 0.f;
        const float4* mp = (const float4*)(Ms + oc * C);
#pragma unroll
        for (int i4 = 0; i4 < C / 4; i4++) {
            float4 m = mp[i4];
            a0 += m.x * v0[i4 * 4 + 0]; a1 += m.x * v1[i4 * 4 + 0];
            a0 += m.y * v0[i4 * 4 + 1]; a1 += m.y * v1[i4 * 4 + 1];
            a0 += m.z * v0[i4 * 4 + 2]; a1 += m.z * v1[i4 * 4 + 2];
            a0 += m.w * v0[i4 * 4 + 3]; a1 += m.w * v1[i4 * 4 + 3];
        }
        float2 o; o.x = a0; o.y = a1;
        *(float2*)(ob + (size_t)oc * NPIX) = o;
    }
}

// ============================================================
extern "C" void kernel_launch(void* const* d_in, const int* in_sizes, int n_in,
                              void* d_out, int out_size) {
    const float* x      = (const float*)d_in[0];
    const float* qkv_w  = (const float*)d_in[1];
    const float* dw_w   = (const float*)d_in[2];
    const float* proj_w = (const float*)d_in[3];
    const float* temp   = (const float*)d_in[4];

    void* smallp = nullptr;
    cudaGetSymbolAddress(&smallp, g_small);
    cudaMemsetAsync(smallp, 0, sizeof(float) * Bc * (C * C + 2 * C));

    k_qkv <<<Bc * (NPIX / 512),          256>>>(x, qkv_w);
    k_dw  <<<Bc * C3 * (HH / DWROWS),    256>>>(dw_w);
    k_gram<<<Bc * (NPIX / CHUNK),        256>>>();
    k_attn<<<Bc,                         256>>>(proj_w, temp);
    k_out <<<Bc * (NPIX / 512),          256>>>((float*)d_out);
}